// round 11
// baseline (speedup 1.0000x reference)
#include <cuda_runtime.h>

#define NB    128
#define DR    144            // fine deposit grid rows (x), with apron
#define DC    144            // fine deposit grid cols (y)
#define DCP   145            // padded smem stride for F in tail (odd -> bank permutation)
#define TBP   129            // padded smem stride for T in tail
#define OFFS  7              // bin index m -> deposit index m + OFFS
#define NTAP  11             // conv radius 5, Gaussian var = 3/4
#define NBLK  148            // 1 CTA/SM
#define NTHR  1024

__device__ float g_fine[DR * DC];   // zeroed at load; re-zeroed by tail each replay

// Gaussian taps, variance 3/4: w[d] = exp(-(d-5)^2 * 2/3)
__constant__ float W[NTAP] = {
    5.77776e-8f, 2.33093e-5f, 2.47875e-3f, 6.94835e-2f, 5.13417e-1f,
    1.0f,
    5.13417e-1f, 6.94835e-2f, 2.47875e-3f, 2.33093e-5f, 5.77776e-8f
};

__global__ void __launch_bounds__(NTHR, 1)
accum_kernel(const float* __restrict__ x,
             const float* __restrict__ ex,
             const float* __restrict__ ey,
             int n) {
    extern __shared__ float D[];    // DR * DC floats
    for (int k = threadIdx.x; k < DR * DC; k += NTHR) D[k] = 0.0f;
    __syncthreads();

    const float bwx = ex[1] - ex[0];
    const float bwy = ey[1] - ey[0];
    const float inv_bwx = 1.0f / bwx;
    const float inv_bwy = 1.0f / bwy;
    const float c0x = 0.5f * (ex[0] + ex[1]);
    const float c0y = 0.5f * (ey[0] + ey[1]);

    for (int p = blockIdx.x * NTHR + threadIdx.x; p < n; p += NBLK * NTHR) {
        float2 pt = __ldg((const float2*)(x + p * 6));   // dims 0,1; 24B row stride
        float ux = (pt.x - c0x) * inv_bwx;   // bin-center units
        float uy = (pt.y - c0y) * inv_bwy;
        float rx = rintf(ux), ry = rintf(uy);
        int mx = (int)rx, my = (int)ry;
        if (((unsigned)(mx + 6) > 139u) | ((unsigned)(my + 6) > 139u)) continue;
        float tx = ux - rx, ty = uy - ry;    // in [-0.5, 0.5]
        // TSC (quadratic) weights: exact moments 0,1; cloud variance = 1/4 exactly
        float am = 0.5f - tx, ap = 0.5f + tx;
        float wx0 = 0.5f * am * am, wx2 = 0.5f * ap * ap, wx1 = 0.75f - tx * tx;
        float bm = 0.5f - ty, bp = 0.5f + ty;
        float wy0 = 0.5f * bm * bm, wy2 = 0.5f * bp * bp, wy1 = 0.75f - ty * ty;
        float* base = &D[(mx + OFFS - 1) * DC + (my + OFFS - 1)];
        atomicAdd(base,              wx0 * wy0);
        atomicAdd(base + 1,          wx0 * wy1);
        atomicAdd(base + 2,          wx0 * wy2);
        atomicAdd(base + DC,         wx1 * wy0);
        atomicAdd(base + DC + 1,     wx1 * wy1);
        atomicAdd(base + DC + 2,     wx1 * wy2);
        atomicAdd(base + 2 * DC,     wx2 * wy0);
        atomicAdd(base + 2 * DC + 1, wx2 * wy1);
        atomicAdd(base + 2 * DC + 2, wx2 * wy2);
    }

    __syncthreads();
    for (int k = threadIdx.x; k < DR * DC; k += NTHR) {
        float v = D[k];
        if (v != 0.0f) atomicAdd(&g_fine[k], v);
    }
}

// Fused tail: conv1 (y) -> conv2 (x) -> sum -> normalize -> rezero. One CTA.
__global__ void __launch_bounds__(1024, 1)
tail_kernel(float* __restrict__ out,
            const float* __restrict__ ex,
            const float* __restrict__ ey) {
    extern __shared__ float S[];
    float* F = S;                 // DR * DCP
    float* T = S + DR * DCP;      // DR * TBP
    __shared__ float red[32];
    __shared__ float s_scale;
    const int t = threadIdx.x;

    // stage fine grid into padded smem (coalesced global read)
    for (int k = t; k < DR * DC; k += 1024)
        F[(k / DC) * DCP + (k % DC)] = g_fine[k];
    __syncthreads();

    // conv1 along j: T[row][j] = sum_d W[d] * F[row][j + d + 2]
    // 576 threads: warp spans consecutive rows -> F reads & T writes conflict-free
    if (t < 576) {
        int row = t % DR;
        int j0 = (t / DR) * 32;
        const float* Fr = &F[row * DCP];
        float* Tr = &T[row * TBP + j0];
        float buf[NTAP];
        #pragma unroll
        for (int d = 0; d < NTAP - 1; ++d) buf[d] = Fr[j0 + 2 + d];
        #pragma unroll
        for (int k = 0; k < 32; ++k) {
            buf[(k + NTAP - 1) % NTAP] = Fr[j0 + 12 + k];   // sliding window
            float s = 0.0f;
            #pragma unroll
            for (int d = 0; d < NTAP; ++d)
                s = fmaf(W[d], buf[(k + d) % NTAP], s);
            Tr[k] = s;
        }
    }
    __syncthreads();

    // conv2 along i, per-thread partial sum (512 threads: j = t&127, 32 rows each)
    float hist[32];
    float ts = 0.0f;
    const int j = t & 127, i0 = (t >> 7) * 32;
    if (t < 512) {
        float buf[NTAP];
        #pragma unroll
        for (int d = 0; d < NTAP - 1; ++d) buf[d] = T[(i0 + 2 + d) * TBP + j];
        #pragma unroll
        for (int k = 0; k < 32; ++k) {
            buf[(k + NTAP - 1) % NTAP] = T[(i0 + 12 + k) * TBP + j];
            float s = 0.0f;
            #pragma unroll
            for (int d = 0; d < NTAP; ++d)
                s = fmaf(W[d], buf[(k + d) % NTAP], s);
            hist[k] = s;
            ts += s;
        }
    }
    // block-wide sum -> scale
    #pragma unroll
    for (int o = 16; o > 0; o >>= 1) ts += __shfl_down_sync(0xffffffffu, ts, o);
    if ((t & 31) == 0) red[t >> 5] = ts;
    __syncthreads();
    if (t < 32) {
        float v = red[t];
        #pragma unroll
        for (int o = 16; o > 0; o >>= 1) v += __shfl_down_sync(0xffffffffu, v, o);
        if (t == 0) {
            float bwx = ex[1] - ex[0], bwy = ey[1] - ey[0];
            s_scale = 1.0f / (v * bwx * bwy);
        }
    }
    __syncthreads();
    if (t < 512) {
        float scale = s_scale;
        #pragma unroll
        for (int k = 0; k < 32; ++k)
            out[(i0 + k) * NB + j] = hist[k] * scale;   // warp-coalesced per k
    }
    // rezero g_fine for next graph replay
    float4 z = make_float4(0.0f, 0.0f, 0.0f, 0.0f);
    float4* gz = reinterpret_cast<float4*>(g_fine);
    for (int k = t; k < (DR * DC) / 4; k += 1024) gz[k] = z;
}

extern "C" void kernel_launch(void* const* d_in, const int* in_sizes, int n_in,
                              void* d_out, int out_size) {
    const float* x  = (const float*)d_in[0];
    const float* ex = (const float*)d_in[1];
    const float* ey = (const float*)d_in[2];
    int n = in_sizes[0] / 6;

    const int SMEM_A = DR * DC * (int)sizeof(float);               // 82944 B
    const int SMEM_T = (DR * DCP + DR * TBP) * (int)sizeof(float); // 157824 B
    cudaFuncSetAttribute(accum_kernel, cudaFuncAttributeMaxDynamicSharedMemorySize, SMEM_A);
    cudaFuncSetAttribute(tail_kernel,  cudaFuncAttributeMaxDynamicSharedMemorySize, SMEM_T);

    accum_kernel<<<NBLK, NTHR, SMEM_A>>>(x, ex, ey, n);
    tail_kernel<<<1, 1024, SMEM_T>>>((float*)d_out, ex, ey);
}

// round 12
// speedup vs baseline: 1.1015x; 1.1015x over previous
#include <cuda_runtime.h>

#define NB    128
#define DR    144            // fine deposit grid rows (x), incl. apron
#define DC    145            // deposit stride (odd -> conv1 row-warp reads bank-permute)
#define TS    133            // intermediate T stride (conv2 reads conflict-free)
#define OFFS  7              // bin index m -> deposit index m + OFFS
#define NTAP  11             // conv radius 5, Gaussian var = 3/4
#define NBLK  148            // 1 CTA/SM
#define NTHR  1024

__device__ float g_hist[NB * NB];     // accumulated; zeroed at load, re-zeroed by tail
__device__ float g_partial[NBLK];     // per-CTA sums (plain stores, no reset needed)

// Gaussian taps, variance 3/4: w[d] = exp(-(d-5)^2 * 2/3)
__constant__ float W[NTAP] = {
    5.77776e-8f, 2.33093e-5f, 2.47875e-3f, 6.94835e-2f, 5.13417e-1f,
    1.0f,
    5.13417e-1f, 6.94835e-2f, 2.47875e-3f, 2.33093e-5f, 5.77776e-8f
};

__global__ void __launch_bounds__(NTHR, 1)
accum_kernel(const float* __restrict__ x,
             const float* __restrict__ ex,
             const float* __restrict__ ey,
             int n) {
    extern __shared__ float S[];
    float* D = S;                 // DR * DC deposit grid
    float* T = S + DR * DC;       // DR * TS  y-convolved intermediate
    __shared__ float red[32];
    const int t = threadIdx.x;

    for (int k = t; k < DR * DC; k += NTHR) D[k] = 0.0f;
    __syncthreads();

    const float bwx = ex[1] - ex[0];
    const float bwy = ey[1] - ey[0];
    const float inv_bwx = 1.0f / bwx;
    const float inv_bwy = 1.0f / bwy;
    const float c0x = 0.5f * (ex[0] + ex[1]);
    const float c0y = 0.5f * (ey[0] + ey[1]);

    // ---- deposit: 9-point TSC (quadratic) cloud, exact variance 1/4 per axis ----
    for (int p = blockIdx.x * NTHR + t; p < n; p += NBLK * NTHR) {
        float2 pt = __ldg((const float2*)(x + p * 6));   // dims 0,1; 24B row stride
        float ux = (pt.x - c0x) * inv_bwx;   // bin-center units
        float uy = (pt.y - c0y) * inv_bwy;
        float rx = rintf(ux), ry = rintf(uy);
        int mx = (int)rx, my = (int)ry;
        if (((unsigned)(mx + 6) > 139u) | ((unsigned)(my + 6) > 139u)) continue;
        float tx = ux - rx, ty = uy - ry;    // in [-0.5, 0.5]
        float am = 0.5f - tx, ap = 0.5f + tx;
        float wx0 = 0.5f * am * am, wx2 = 0.5f * ap * ap, wx1 = 0.75f - tx * tx;
        float bm = 0.5f - ty, bp = 0.5f + ty;
        float wy0 = 0.5f * bm * bm, wy2 = 0.5f * bp * bp, wy1 = 0.75f - ty * ty;
        float* base = &D[(mx + OFFS - 1) * DC + (my + OFFS - 1)];
        atomicAdd(base,              wx0 * wy0);
        atomicAdd(base + 1,          wx0 * wy1);
        atomicAdd(base + 2,          wx0 * wy2);
        atomicAdd(base + DC,         wx1 * wy0);
        atomicAdd(base + DC + 1,     wx1 * wy1);
        atomicAdd(base + DC + 2,     wx1 * wy2);
        atomicAdd(base + 2 * DC,     wx2 * wy0);
        atomicAdd(base + 2 * DC + 1, wx2 * wy1);
        atomicAdd(base + 2 * DC + 2, wx2 * wy2);
    }
    __syncthreads();

    // ---- conv1 (y): T[row][j] = sum_d W[d] * D[row][j+d+2], 576 threads ----
    if (t < 576) {
        int row = t % DR;
        int j0 = (t / DR) * 32;
        const float* Dr = &D[row * DC];
        float* Tr = &T[row * TS + j0];
        float buf[NTAP];
        #pragma unroll
        for (int d = 0; d < NTAP - 1; ++d) buf[d] = Dr[j0 + 2 + d];
        #pragma unroll
        for (int k = 0; k < 32; ++k) {
            buf[(k + NTAP - 1) % NTAP] = Dr[j0 + 12 + k];   // sliding window
            float s = 0.0f;
            #pragma unroll
            for (int d = 0; d < NTAP; ++d)
                s = fmaf(W[d], buf[(k + d) % NTAP], s);
            Tr[k] = s;
        }
    }
    __syncthreads();

    // ---- conv2 (x) + flush + partial sum, 512 threads ----
    float ts = 0.0f;
    if (t < 512) {
        const int j = t & 127, i0 = (t >> 7) * 32;
        float buf[NTAP];
        #pragma unroll
        for (int d = 0; d < NTAP - 1; ++d) buf[d] = T[(i0 + 2 + d) * TS + j];
        #pragma unroll
        for (int k = 0; k < 32; ++k) {
            buf[(k + NTAP - 1) % NTAP] = T[(i0 + 12 + k) * TS + j];
            float s = 0.0f;
            #pragma unroll
            for (int d = 0; d < NTAP; ++d)
                s = fmaf(W[d], buf[(k + d) % NTAP], s);
            ts += s;
            if (s != 0.0f)
                atomicAdd(&g_hist[(i0 + k) * NB + j], s);   // warp-coalesced REDG
        }
    }
    // block-reduce ts -> g_partial[blockIdx.x] (plain store, no reset race)
    #pragma unroll
    for (int o = 16; o > 0; o >>= 1) ts += __shfl_down_sync(0xffffffffu, ts, o);
    if ((t & 31) == 0) red[t >> 5] = ts;
    __syncthreads();
    if (t < 32) {
        float v = red[t];
        #pragma unroll
        for (int o = 16; o > 0; o >>= 1) v += __shfl_down_sync(0xffffffffu, v, o);
        if (t == 0) g_partial[blockIdx.x] = v;
    }
}

// Wide tail: reduce partials, normalize, rezero g_hist. 16 CTAs x 256 thr.
__global__ void tail_kernel(float* __restrict__ out,
                            const float* __restrict__ ex,
                            const float* __restrict__ ey) {
    __shared__ float red[8];
    __shared__ float s_scale;
    const int t = threadIdx.x;

    float v = (t < NBLK) ? g_partial[t] : 0.0f;
    #pragma unroll
    for (int o = 16; o > 0; o >>= 1) v += __shfl_down_sync(0xffffffffu, v, o);
    if ((t & 31) == 0) red[t >> 5] = v;
    __syncthreads();
    if (t < 8) {
        float w = red[t];
        #pragma unroll
        for (int o = 4; o > 0; o >>= 1) w += __shfl_down_sync(0x000000ffu, w, o);
        if (t == 0) {
            float bwx = ex[1] - ex[0], bwy = ey[1] - ey[0];
            s_scale = 1.0f / (w * bwx * bwy);
        }
    }
    __syncthreads();
    const float scale = s_scale;
    int base = blockIdx.x * 1024;
    #pragma unroll
    for (int i = 0; i < 4; ++i) {
        int idx = base + i * 256 + t;
        out[idx] = g_hist[idx] * scale;
        g_hist[idx] = 0.0f;       // reset for next graph replay
    }
}

extern "C" void kernel_launch(void* const* d_in, const int* in_sizes, int n_in,
                              void* d_out, int out_size) {
    const float* x  = (const float*)d_in[0];
    const float* ex = (const float*)d_in[1];
    const float* ey = (const float*)d_in[2];
    int n = in_sizes[0] / 6;

    const int SMEM = (DR * DC + DR * TS) * (int)sizeof(float);   // 160128 B
    cudaFuncSetAttribute(accum_kernel, cudaFuncAttributeMaxDynamicSharedMemorySize, SMEM);

    accum_kernel<<<NBLK, NTHR, SMEM>>>(x, ex, ey, n);
    tail_kernel<<<16, 256>>>((float*)d_out, ex, ey);
}

// round 13
// speedup vs baseline: 1.3333x; 1.2104x over previous
#include <cuda_runtime.h>

#define NB    128
#define DR    144            // fine deposit grid rows (x), incl. apron
#define DC    145            // deposit stride (odd -> conv1 row-warp reads bank-permute)
#define TS    133            // intermediate T stride (conv2 reads conflict-free)
#define OFFS  7              // bin index m -> deposit index m + OFFS
#define NTAP  9              // conv radius 4, Gaussian var = 3/4 (±5 taps ~5.8e-8 dropped)
#define NBLK  148            // 1 CTA/SM
#define NTHR  1024

__device__ float g_hist[NB * NB];     // accumulated; zeroed at load, re-zeroed by tail
__device__ float g_partial[NBLK];     // per-CTA sums (plain stores, no reset needed)

// Gaussian taps, variance 3/4: w[k] = exp(-(k-4)^2 * 2/3)
__constant__ float W[NTAP] = {
    2.33093e-5f, 2.47875e-3f, 6.94835e-2f, 5.13417e-1f,
    1.0f,
    5.13417e-1f, 6.94835e-2f, 2.47875e-3f, 2.33093e-5f
};

__global__ void __launch_bounds__(NTHR, 1)
accum_kernel(const float* __restrict__ x,
             const float* __restrict__ ex,
             const float* __restrict__ ey,
             int n) {
    extern __shared__ float S[];
    float* D = S;                 // DR * DC deposit grid
    float* T = S + DR * DC;       // DR * TS  y-convolved intermediate
    __shared__ float red[32];
    const int t = threadIdx.x;

    for (int k = t; k < DR * DC; k += NTHR) D[k] = 0.0f;
    __syncthreads();

    const float bwx = ex[1] - ex[0];
    const float bwy = ey[1] - ey[0];
    const float inv_bwx = 1.0f / bwx;
    const float inv_bwy = 1.0f / bwy;
    const float c0x = 0.5f * (ex[0] + ex[1]);
    const float c0y = 0.5f * (ey[0] + ey[1]);

    // ---- deposit: 9-point TSC (quadratic) cloud, exact variance 1/4 per axis ----
    for (int p = blockIdx.x * NTHR + t; p < n; p += NBLK * NTHR) {
        float2 pt = __ldg((const float2*)(x + p * 6));   // dims 0,1; 24B row stride
        float ux = (pt.x - c0x) * inv_bwx;   // bin-center units
        float uy = (pt.y - c0y) * inv_bwy;
        float rx = rintf(ux), ry = rintf(uy);
        int mx = (int)rx, my = (int)ry;
        if (((unsigned)(mx + 6) > 139u) | ((unsigned)(my + 6) > 139u)) continue;
        float tx = ux - rx, ty = uy - ry;    // in [-0.5, 0.5]
        float am = 0.5f - tx, ap = 0.5f + tx;
        float wx0 = 0.5f * am * am, wx2 = 0.5f * ap * ap, wx1 = 0.75f - tx * tx;
        float bm = 0.5f - ty, bp = 0.5f + ty;
        float wy0 = 0.5f * bm * bm, wy2 = 0.5f * bp * bp, wy1 = 0.75f - ty * ty;
        float* base = &D[(mx + OFFS - 1) * DC + (my + OFFS - 1)];
        atomicAdd(base,              wx0 * wy0);
        atomicAdd(base + 1,          wx0 * wy1);
        atomicAdd(base + 2,          wx0 * wy2);
        atomicAdd(base + DC,         wx1 * wy0);
        atomicAdd(base + DC + 1,     wx1 * wy1);
        atomicAdd(base + DC + 2,     wx1 * wy2);
        atomicAdd(base + 2 * DC,     wx2 * wy0);
        atomicAdd(base + 2 * DC + 1, wx2 * wy1);
        atomicAdd(base + 2 * DC + 2, wx2 * wy2);
    }
    __syncthreads();

    // ---- conv1 (y): T[row][j] = sum_d W[d] * D[row][j+d+3], 576 threads ----
    if (t < 576) {
        int row = t % DR;
        int j0 = (t / DR) * 32;
        const float* Dr = &D[row * DC];
        float* Tr = &T[row * TS + j0];
        float buf[NTAP];
        #pragma unroll
        for (int d = 0; d < NTAP - 1; ++d) buf[d] = Dr[j0 + 3 + d];
        #pragma unroll
        for (int k = 0; k < 32; ++k) {
            buf[(k + NTAP - 1) % NTAP] = Dr[j0 + 11 + k];   // sliding window
            float s = 0.0f;
            #pragma unroll
            for (int d = 0; d < NTAP; ++d)
                s = fmaf(W[d], buf[(k + d) % NTAP], s);
            Tr[k] = s;
        }
    }
    __syncthreads();

    // ---- conv2 (x) + flush + partial sum, 512 threads ----
    float ts = 0.0f;
    if (t < 512) {
        const int j = t & 127, i0 = (t >> 7) * 32;
        float buf[NTAP];
        #pragma unroll
        for (int d = 0; d < NTAP - 1; ++d) buf[d] = T[(i0 + 3 + d) * TS + j];
        #pragma unroll
        for (int k = 0; k < 32; ++k) {
            buf[(k + NTAP - 1) % NTAP] = T[(i0 + 11 + k) * TS + j];
            float s = 0.0f;
            #pragma unroll
            for (int d = 0; d < NTAP; ++d)
                s = fmaf(W[d], buf[(k + d) % NTAP], s);
            ts += s;
            atomicAdd(&g_hist[(i0 + k) * NB + j], s);   // warp-coalesced REDG
        }
    }
    // block-reduce ts -> g_partial[blockIdx.x] (plain store, no reset race)
    #pragma unroll
    for (int o = 16; o > 0; o >>= 1) ts += __shfl_down_sync(0xffffffffu, ts, o);
    if ((t & 31) == 0) red[t >> 5] = ts;
    __syncthreads();
    if (t < 32) {
        float v = red[t];
        #pragma unroll
        for (int o = 16; o > 0; o >>= 1) v += __shfl_down_sync(0xffffffffu, v, o);
        if (t == 0) g_partial[blockIdx.x] = v;
    }
}

// Flat tail: 64 CTAs; each redundantly reduces the 148 partials (no inter-CTA
// dependency), then scales/writes/rezeros its own 256-element slice.
__global__ void tail_kernel(float* __restrict__ out,
                            const float* __restrict__ ex,
                            const float* __restrict__ ey) {
    __shared__ float red[5];
    __shared__ float s_scale;
    const int t = threadIdx.x;

    float v = (t < NBLK) ? g_partial[t] : 0.0f;
    #pragma unroll
    for (int o = 16; o > 0; o >>= 1) v += __shfl_down_sync(0xffffffffu, v, o);
    if ((t & 31) == 0 && t < 160) red[t >> 5] = v;
    __syncthreads();
    if (t == 0) {
        float w = red[0] + red[1] + red[2] + red[3] + red[4];
        float bwx = ex[1] - ex[0], bwy = ey[1] - ey[0];
        s_scale = 1.0f / (w * bwx * bwy);
    }
    __syncthreads();
    int idx = blockIdx.x * 256 + t;
    out[idx] = g_hist[idx] * s_scale;
    g_hist[idx] = 0.0f;       // reset for next graph replay
}

extern "C" void kernel_launch(void* const* d_in, const int* in_sizes, int n_in,
                              void* d_out, int out_size) {
    const float* x  = (const float*)d_in[0];
    const float* ex = (const float*)d_in[1];
    const float* ey = (const float*)d_in[2];
    int n = in_sizes[0] / 6;

    const int SMEM = (DR * DC + DR * TS) * (int)sizeof(float);   // 160128 B
    cudaFuncSetAttribute(accum_kernel, cudaFuncAttributeMaxDynamicSharedMemorySize, SMEM);

    accum_kernel<<<NBLK, NTHR, SMEM>>>(x, ex, ey, n);
    tail_kernel<<<(NB * NB) / 256, 256>>>((float*)d_out, ex, ey);
}

// round 14
// speedup vs baseline: 1.3401x; 1.0051x over previous
#include <cuda_runtime.h>
#include <cuda_fp16.h>

#define NB    128
#define DR    144            // fine deposit grid rows (x), incl. apron
#define SP2   73             // deposit row stride in half2 pairs (odd -> bank permute)
#define SH    (SP2*2)        // row stride in halves = 146
#define TS    133            // intermediate T stride (f32, conv2 reads conflict-free)
#define OFFS  7              // bin index m -> deposit index m + OFFS
#define NTAP  9              // conv radius 4, Gaussian var = 3/4
#define NBLK  148            // 1 CTA/SM
#define NTHR  1024

__device__ float g_hist[NB * NB];     // accumulated; zeroed at load, re-zeroed by tail
__device__ float g_partial[NBLK];     // per-CTA sums (plain stores)

// Gaussian taps, variance 3/4: w[k] = exp(-(k-4)^2 * 2/3)
__constant__ float W[NTAP] = {
    2.33093e-5f, 2.47875e-3f, 6.94835e-2f, 5.13417e-1f,
    1.0f,
    5.13417e-1f, 6.94835e-2f, 2.47875e-3f, 2.33093e-5f
};

__global__ void __launch_bounds__(NTHR, 1)
accum_kernel(const float* __restrict__ x,
             const float* __restrict__ ex,
             const float* __restrict__ ey,
             int n) {
    extern __shared__ float S[];
    __half2* Dh = (__half2*)S;                    // DR * SP2 half2 deposit grid
    const __half* Ds = (const __half*)S;          // same memory, scalar half view
    float* T = S + (DR * SP2);                    // DR * TS f32 intermediate (half2=1 float)
    __shared__ float red[32];
    const int t = threadIdx.x;

    for (int k = t; k < DR * SP2; k += NTHR)
        ((unsigned*)S)[k] = 0u;                   // zero deposit grid
    __syncthreads();

    const float bwx = ex[1] - ex[0];
    const float bwy = ey[1] - ey[0];
    const float inv_bwx = 1.0f / bwx;
    const float inv_bwy = 1.0f / bwy;
    const float c0x = 0.5f * (ex[0] + ex[1]);
    const float c0y = 0.5f * (ey[0] + ey[1]);

    // ---- deposit: TSC 3x3 cloud (t-invariant variance 1/4), f16x2 packed ----
    for (int p = blockIdx.x * NTHR + t; p < n; p += NBLK * NTHR) {
        float2 pt = __ldg((const float2*)(x + p * 6));   // dims 0,1; 24B row stride
        float ux = (pt.x - c0x) * inv_bwx;   // bin-center units
        float uy = (pt.y - c0y) * inv_bwy;
        float rx = rintf(ux), ry = rintf(uy);
        int mx = (int)rx, my = (int)ry;
        if (((unsigned)(mx + 6) > 139u) | ((unsigned)(my + 6) > 139u)) continue;
        float tx = ux - rx, ty = uy - ry;    // in [-0.5, 0.5]
        float am = 0.5f - tx, ap = 0.5f + tx;
        float wx0 = 0.5f * am * am, wx2 = 0.5f * ap * ap, wx1 = 0.75f - tx * tx;
        float bm = 0.5f - ty, bp = 0.5f + ty;
        float wy0 = 0.5f * bm * bm, wy2 = 0.5f * bp * bp, wy1 = 0.75f - ty * ty;
        int q = my + OFFS - 1;                       // first y cell (half index)
        int e = q & 1;
        // alignment patterns: pairA = (a0,a1), pairB = (b0,b1)
        float a0 = e ? 0.0f : wy0;
        float a1 = e ? wy0  : wy1;
        float b0 = e ? wy1  : wy2;
        float b1 = e ? wy2  : 0.0f;
        int base = (mx + OFFS - 1) * SP2 + (q >> 1);
        atomicAdd(&Dh[base],           __floats2half2_rn(wx0 * a0, wx0 * a1));
        atomicAdd(&Dh[base + 1],       __floats2half2_rn(wx0 * b0, wx0 * b1));
        atomicAdd(&Dh[base + SP2],     __floats2half2_rn(wx1 * a0, wx1 * a1));
        atomicAdd(&Dh[base + SP2 + 1], __floats2half2_rn(wx1 * b0, wx1 * b1));
        atomicAdd(&Dh[base + 2*SP2],   __floats2half2_rn(wx2 * a0, wx2 * a1));
        atomicAdd(&Dh[base + 2*SP2+1], __floats2half2_rn(wx2 * b0, wx2 * b1));
    }
    __syncthreads();

    // ---- conv1 (y): T[row][j] = sum_d W[d] * D[row][j+d+3], 576 threads ----
    if (t < 576) {
        int row = t % DR;
        int j0 = (t / DR) * 32;
        const __half* Dr = &Ds[row * SH];
        float* Tr = &T[row * TS + j0];
        float buf[NTAP];
        #pragma unroll
        for (int d = 0; d < NTAP - 1; ++d) buf[d] = __half2float(Dr[j0 + 3 + d]);
        #pragma unroll
        for (int k = 0; k < 32; ++k) {
            buf[(k + NTAP - 1) % NTAP] = __half2float(Dr[j0 + 11 + k]);
            float s = 0.0f;
            #pragma unroll
            for (int d = 0; d < NTAP; ++d)
                s = fmaf(W[d], buf[(k + d) % NTAP], s);
            Tr[k] = s;
        }
    }
    __syncthreads();

    // ---- conv2 (x) + flush + partial sum, 512 threads ----
    float ts = 0.0f;
    if (t < 512) {
        const int j = t & 127, i0 = (t >> 7) * 32;
        float buf[NTAP];
        #pragma unroll
        for (int d = 0; d < NTAP - 1; ++d) buf[d] = T[(i0 + 3 + d) * TS + j];
        #pragma unroll
        for (int k = 0; k < 32; ++k) {
            buf[(k + NTAP - 1) % NTAP] = T[(i0 + 11 + k) * TS + j];
            float s = 0.0f;
            #pragma unroll
            for (int d = 0; d < NTAP; ++d)
                s = fmaf(W[d], buf[(k + d) % NTAP], s);
            ts += s;
            atomicAdd(&g_hist[(i0 + k) * NB + j], s);   // warp-coalesced REDG
        }
    }
    // block-reduce ts -> g_partial[blockIdx.x]
    #pragma unroll
    for (int o = 16; o > 0; o >>= 1) ts += __shfl_down_sync(0xffffffffu, ts, o);
    if ((t & 31) == 0) red[t >> 5] = ts;
    __syncthreads();
    if (t < 32) {
        float v = red[t];
        #pragma unroll
        for (int o = 16; o > 0; o >>= 1) v += __shfl_down_sync(0xffffffffu, v, o);
        if (t == 0) g_partial[blockIdx.x] = v;
    }
}

// Flat tail: 64 CTAs; each redundantly reduces the 148 partials, then
// scales/writes/rezeros its own 256-element slice.
__global__ void tail_kernel(float* __restrict__ out,
                            const float* __restrict__ ex,
                            const float* __restrict__ ey) {
    __shared__ float red[5];
    __shared__ float s_scale;
    const int t = threadIdx.x;

    float v = (t < NBLK) ? g_partial[t] : 0.0f;
    #pragma unroll
    for (int o = 16; o > 0; o >>= 1) v += __shfl_down_sync(0xffffffffu, v, o);
    if ((t & 31) == 0 && t < 160) red[t >> 5] = v;
    __syncthreads();
    if (t == 0) {
        float w = red[0] + red[1] + red[2] + red[3] + red[4];
        float bwx = ex[1] - ex[0], bwy = ey[1] - ey[0];
        s_scale = 1.0f / (w * bwx * bwy);
    }
    __syncthreads();
    int idx = blockIdx.x * 256 + t;
    out[idx] = g_hist[idx] * s_scale;
    g_hist[idx] = 0.0f;       // reset for next graph replay
}

extern "C" void kernel_launch(void* const* d_in, const int* in_sizes, int n_in,
                              void* d_out, int out_size) {
    const float* x  = (const float*)d_in[0];
    const float* ex = (const float*)d_in[1];
    const float* ey = (const float*)d_in[2];
    int n = in_sizes[0] / 6;

    const int SMEM = (DR * SP2 + DR * TS) * (int)sizeof(float);   // 118656 B
    cudaFuncSetAttribute(accum_kernel, cudaFuncAttributeMaxDynamicSharedMemorySize, SMEM);

    accum_kernel<<<NBLK, NTHR, SMEM>>>(x, ex, ey, n);
    tail_kernel<<<(NB * NB) / 256, 256>>>((float*)d_out, ex, ey);
}